// round 3
// baseline (speedup 1.0000x reference)
#include <cuda_runtime.h>
#include <cstdint>

// Problem constants
#define HWsz 16384
#define Cc   64
#define Bb   8
#define NPIX (Bb * HWsz)   // 131072 pixels

// -------- scratch --------
__device__ float  g_xt[(size_t)NPIX * Cc];     // NHWC x
__device__ float  g_wq[576 * 64];              // [(c*9+k)][o]
__device__ int4   g_ci[(size_t)NPIX * 9];      // bilinear corner indices
__device__ float4 g_cw[(size_t)NPIX * 9];      // corner weights (mask folded)

// -------- f32x2 helpers --------
__device__ __forceinline__ void ffma2(unsigned long long& d, unsigned long long a, unsigned long long b) {
    asm("fma.rn.f32x2 %0, %1, %2, %0;" : "+l"(d) : "l"(a), "l"(b));
}
__device__ __forceinline__ unsigned long long pack2(float x, float y) {
    unsigned long long r; asm("mov.b64 %0, {%1, %2};" : "=l"(r) : "f"(x), "f"(y)); return r;
}
__device__ __forceinline__ float2 unpack2(unsigned long long v) {
    float2 f; asm("mov.b64 {%0, %1}, %2;" : "=f"(f.x), "=f"(f.y) : "l"(v)); return f;
}

// ---------------- kernel 1: NCHW -> NHWC ----------------
__global__ void __launch_bounds__(256) k_transpose(const float* __restrict__ x) {
    __shared__ float sh[64][33];
    int blk = blockIdx.x;
    int b   = blk >> 9;
    int hw0 = (blk & 511) << 5;
    int t = threadIdx.x;
#pragma unroll
    for (int i = 0; i < 8; i++) {
        int e = t + i * 256;
        int c = e >> 5, wp = e & 31;
        sh[c][wp] = x[((size_t)(b * 64 + c) << 14) + hw0 + wp];
    }
    __syncthreads();
#pragma unroll
    for (int i = 0; i < 8; i++) {
        int e = t + i * 256;
        int wp = e >> 6, c = e & 63;
        g_xt[(((size_t)b << 14) + hw0 + wp) * 64 + c] = sh[c][wp];
    }
}

// ---------------- kernel 2: repack w_conv ----------------
__global__ void k_wq(const float* __restrict__ w_conv) {
    int t = blockIdx.x * 256 + threadIdx.x;
    if (t < 64 * 576) {
        int o   = t / 576;
        int rem = t - o * 576;
        g_wq[rem * 64 + o] = w_conv[t];
    }
}

// ---------------- kernel 3: offset+mask conv + corner precompute ----------------
// shW2 layout: [(kk*64+c)*28 + ch], ch 0..26 real (0..17 offset, 18..26 mask), 27 = pad 0.
__global__ void __launch_bounds__(128) k_conv(const float* __restrict__ x,
                                              const float* __restrict__ w_off,
                                              const float* __restrict__ w_msk) {
    extern __shared__ float shW[];   // 9*64*28 = 16128 floats
    int t = threadIdx.x;
    for (int i = t; i < 9 * 64; i += 128) shW[i * 28 + 27] = 0.f;
    for (int i = t; i < 27 * 576; i += 128) {
        int ch = i / 576;
        int r  = i - ch * 576;     // c*9+kk
        int c  = r / 9, kk = r - c * 9;
        float v = (ch < 18) ? w_off[i] : w_msk[i - 18 * 576];
        shW[(kk * 64 + c) * 28 + ch] = v;
    }
    __syncthreads();

    int p0  = blockIdx.x * 256 + t;
    int b   = p0 >> 14;
    int hw0 = p0 & 16383;
    int h0  = hw0 >> 7, w0c = hw0 & 127;
    int h1  = h0 + 1;
    const float* xb = x + ((size_t)b << 20);

    unsigned long long a0[14], a1[14];
#pragma unroll
    for (int i = 0; i < 14; i++) { a0[i] = 0ull; a1[i] = 0ull; }

#pragma unroll 1
    for (int kk = 0; kk < 9; kk++) {
        int dy = kk / 3 - 1, dx = kk % 3 - 1;
        int hh0 = h0 + dy, ww = w0c + dx;
        int hh1 = h1 + dy;
        bool okx = (unsigned)ww < 128u;
        bool ok0 = okx && ((unsigned)hh0 < 128u);
        bool ok1 = okx && ((unsigned)hh1 < 128u);
        int off0 = hh0 * 128 + ww;
        int off1 = hh1 * 128 + ww;
        const float* wbase = shW + kk * 64 * 28;
#pragma unroll 2
        for (int c = 0; c < 64; c++) {
            float v0 = ok0 ? xb[c * 16384 + off0] : 0.f;
            float v1 = ok1 ? xb[c * 16384 + off1] : 0.f;
            unsigned long long v0d = pack2(v0, v0);
            unsigned long long v1d = pack2(v1, v1);
            const ulonglong2* wrow = (const ulonglong2*)(wbase + c * 28);
#pragma unroll
            for (int q = 0; q < 7; q++) {
                ulonglong2 wp = wrow[q];
                ffma2(a0[2 * q],     v0d, wp.x);
                ffma2(a0[2 * q + 1], v0d, wp.y);
                ffma2(a1[2 * q],     v1d, wp.x);
                ffma2(a1[2 * q + 1], v1d, wp.y);
            }
        }
    }

    float r0[28], r1[28];
#pragma unroll
    for (int q = 0; q < 14; q++) {
        float2 e0 = unpack2(a0[q]); r0[2 * q] = e0.x; r0[2 * q + 1] = e0.y;
        float2 e1 = unpack2(a1[q]); r1[2 * q] = e1.x; r1[2 * q + 1] = e1.y;
    }

    auto emit = [&](int p, int h, int w, const float* acc) {
#pragma unroll
        for (int k = 0; k < 9; k++) {
            float oy = acc[2 * k], ox = acc[2 * k + 1];
            float m  = 1.f / (1.f + __expf(-acc[18 + k]));
            float py = (float)(h + k / 3 - 1) + oy;
            float px = (float)(w + k % 3 - 1) + ox;
            float y0f = floorf(py), x0f = floorf(px);
            float wy1 = py - y0f, wy0 = 1.f - wy1;
            float wx1 = px - x0f, wx0 = 1.f - wx1;
            int y0 = (int)y0f, x0i = (int)x0f;
            int y1 = y0 + 1, x1i = x0i + 1;
            bool vy0 = (unsigned)y0  < 128u, vy1 = (unsigned)y1  < 128u;
            bool vx0 = (unsigned)x0i < 128u, vx1 = (unsigned)x1i < 128u;
            int cy0 = min(max(y0, 0), 127), cy1 = min(max(y1, 0), 127);
            int cx0 = min(max(x0i, 0), 127), cx1 = min(max(x1i, 0), 127);
            int4 ci; float4 cw;
            ci.x = cy0 * 128 + cx0; cw.x = (vy0 && vx0) ? m * wy0 * wx0 : 0.f;
            ci.y = cy0 * 128 + cx1; cw.y = (vy0 && vx1) ? m * wy0 * wx1 : 0.f;
            ci.z = cy1 * 128 + cx0; cw.z = (vy1 && vx0) ? m * wy1 * wx0 : 0.f;
            ci.w = cy1 * 128 + cx1; cw.w = (vy1 && vx1) ? m * wy1 * wx1 : 0.f;
            g_ci[(size_t)p * 9 + k] = ci;
            g_cw[(size_t)p * 9 + k] = cw;
        }
    };
    emit(p0,       h0, w0c, r0);
    emit(p0 + 128, h1, w0c, r1);
}

// ---------------- kernel 4: deformable gather + contraction ----------------
// CTA = 64 px, 256 threads. FOUR c-chunks of 16 channels (smem 93KB -> 2 CTA/SM).
// Phase B: 64px x 64o tile, thread tile 4px x 4o, j-vectorized x4, FFMA2 packed over o.
#define SSTR 148   // sS row stride (144 + 4 pad), multiple of 4 -> float4 aligned
__global__ void __launch_bounds__(256) k_deform(float* __restrict__ out) {
    extern __shared__ float smem[];
    float*  sS  = smem;                          // 64*148
    float*  sW  = smem + 64 * SSTR;              // 144*64
    int4*   sCI = (int4*)(sW + 144 * 64);        // 576
    float4* sCW = (float4*)(sCI + 576);          // 576

    int t = threadIdx.x;
    int warp = t >> 5, lane = t & 31;
    int half = lane >> 4, cl = lane & 15;
    int P0 = blockIdx.x << 6;
    int b  = P0 >> 14;
    int hwbase = P0 & 16383;

    for (int i = t; i < 576; i += 256) {
        sCI[i] = g_ci[(size_t)P0 * 9 + i];
        sCW[i] = g_cw[(size_t)P0 * 9 + i];
    }
    const float* xb = g_xt + ((size_t)b << 20);

    unsigned long long acc[4][2];
#pragma unroll
    for (int r = 0; r < 4; r++) { acc[r][0] = 0ull; acc[r][1] = 0ull; }
    int og = t & 15;   // o group: o = og*4 .. og*4+3
    int pg = t >> 4;   // px group: px = pg*4 .. pg*4+3

#pragma unroll 1
    for (int jc = 0; jc < 4; jc++) {
        __syncthreads();   // previous phase B done before overwriting sS/sW
        // load W chunk: global j = jc*144 + jl
        for (int i = t; i < 144 * 64; i += 256) sW[i] = g_wq[jc * (144 * 64) + i];
        int c0 = jc << 4;
        // gather: each warp-iter covers 2 (k,px) pairs, 16 channels per half-warp
        for (int it = warp; it < 288; it += 8) {
            int pair = it * 2 + half;        // 0..575 = k*64 + px
            int k  = pair >> 6;
            int px = pair & 63;
            int4   ci = sCI[px * 9 + k];
            float4 cw = sCW[px * 9 + k];
            int cc = c0 + cl;
            float v = cw.x * xb[ci.x * 64 + cc]
                    + cw.y * xb[ci.y * 64 + cc]
                    + cw.z * xb[ci.z * 64 + cc]
                    + cw.w * xb[ci.w * 64 + cc];
            sS[px * SSTR + cl * 9 + k] = v;   // local j = cl*9+k in [0,144)
        }
        __syncthreads();
        // phase B: S[64x144] * W[144x64]
        const float* srow0 = sS + (pg * 4 + 0) * SSTR;
        const float* srow1 = sS + (pg * 4 + 1) * SSTR;
        const float* srow2 = sS + (pg * 4 + 2) * SSTR;
        const float* srow3 = sS + (pg * 4 + 3) * SSTR;
#pragma unroll 4
        for (int j = 0; j < 144; j += 4) {
            ulonglong2 w0 = ((const ulonglong2*)(sW + (j + 0) * 64))[og];
            ulonglong2 w1 = ((const ulonglong2*)(sW + (j + 1) * 64))[og];
            ulonglong2 w2 = ((const ulonglong2*)(sW + (j + 2) * 64))[og];
            ulonglong2 w3 = ((const ulonglong2*)(sW + (j + 3) * 64))[og];
            float4 s0 = *(const float4*)(srow0 + j);
            float4 s1 = *(const float4*)(srow1 + j);
            float4 s2 = *(const float4*)(srow2 + j);
            float4 s3 = *(const float4*)(srow3 + j);
#define STEP(r, s)                                            \
            {                                                 \
                unsigned long long d;                         \
                d = pack2(s.x, s.x); ffma2(acc[r][0], d, w0.x); ffma2(acc[r][1], d, w0.y); \
                d = pack2(s.y, s.y); ffma2(acc[r][0], d, w1.x); ffma2(acc[r][1], d, w1.y); \
                d = pack2(s.z, s.z); ffma2(acc[r][0], d, w2.x); ffma2(acc[r][1], d, w2.y); \
                d = pack2(s.w, s.w); ffma2(acc[r][0], d, w3.x); ffma2(acc[r][1], d, w3.y); \
            }
            STEP(0, s0) STEP(1, s1) STEP(2, s2) STEP(3, s3)
#undef STEP
        }
    }

    // unpack: acc[r][0] -> o = og*4+0, og*4+1 ; acc[r][1] -> og*4+2, og*4+3
    float2 u[4][2];
#pragma unroll
    for (int r = 0; r < 4; r++) { u[r][0] = unpack2(acc[r][0]); u[r][1] = unpack2(acc[r][1]); }

    size_t obase = ((size_t)b << 20) + hwbase + (pg << 2);
    int o0 = og << 2;
    *(float4*)(out + obase + (size_t)(o0 + 0) * 16384) = make_float4(u[0][0].x, u[1][0].x, u[2][0].x, u[3][0].x);
    *(float4*)(out + obase + (size_t)(o0 + 1) * 16384) = make_float4(u[0][0].y, u[1][0].y, u[2][0].y, u[3][0].y);
    *(float4*)(out + obase + (size_t)(o0 + 2) * 16384) = make_float4(u[0][1].x, u[1][1].x, u[2][1].x, u[3][1].x);
    *(float4*)(out + obase + (size_t)(o0 + 3) * 16384) = make_float4(u[0][1].y, u[1][1].y, u[2][1].y, u[3][1].y);
}

// ---------------- launch ----------------
extern "C" void kernel_launch(void* const* d_in, const int* in_sizes, int n_in,
                              void* d_out, int out_size) {
    (void)in_sizes; (void)n_in; (void)out_size;
    const float* x      = (const float*)d_in[0];
    const float* w_conv = (const float*)d_in[1];
    const float* w_off  = (const float*)d_in[2];
    const float* w_msk  = (const float*)d_in[3];
    float* out = (float*)d_out;

    const int convSmem   = 9 * 64 * 28 * 4;                        // 64512 B
    const int deformSmem = (64 * SSTR + 144 * 64) * 4 + 576 * 32;  // 93184 B
    cudaFuncSetAttribute(k_conv,   cudaFuncAttributeMaxDynamicSharedMemorySize, convSmem);
    cudaFuncSetAttribute(k_deform, cudaFuncAttributeMaxDynamicSharedMemorySize, deformSmem);

    k_transpose<<<4096, 256>>>(x);
    k_wq<<<(64 * 576 + 255) / 256, 256>>>(w_conv);
    k_conv<<<512, 128, convSmem>>>(x, w_off, w_msk);
    k_deform<<<2048, 256, deformSmem>>>(out);
}

// round 5
// speedup vs baseline: 1.6260x; 1.6260x over previous
#include <cuda_runtime.h>
#include <cuda_bf16.h>
#include <cstdint>

#define HWsz 16384
#define NPIX (8 * HWsz)   // 131072 pixels

// -------- scratch --------
__device__ float    g_xt[(size_t)NPIX * 64];           // NHWC x
__device__ __align__(16) uint32_t g_wqs[9 * 4096];     // per tap: 16KB = hi(8KB)+lo(8KB) swizzled 64x64 bf16 tiles
__device__ int4     g_ci[(size_t)NPIX * 9];            // bilinear corner indices
__device__ float4   g_cw[(size_t)NPIX * 9];            // corner weights (mask folded)

// -------- helpers --------
__device__ __forceinline__ void ffma2(unsigned long long& d, unsigned long long a, unsigned long long b) {
    asm("fma.rn.f32x2 %0, %1, %2, %0;" : "+l"(d) : "l"(a), "l"(b));
}
__device__ __forceinline__ unsigned long long pack2(float x, float y) {
    unsigned long long r; asm("mov.b64 %0, {%1, %2};" : "=l"(r) : "f"(x), "f"(y)); return r;
}
__device__ __forceinline__ float2 unpack2(unsigned long long v) {
    float2 f; asm("mov.b64 {%0, %1}, %2;" : "=f"(f.x), "=f"(f.y) : "l"(v)); return f;
}
__device__ __forceinline__ uint32_t smem_u32(const void* p) {
    return (uint32_t)__cvta_generic_to_shared(p);
}
__device__ __forceinline__ void sts64(uint32_t addr, uint32_t a, uint32_t b) {
    asm volatile("st.shared.v2.b32 [%0], {%1, %2};" :: "r"(addr), "r"(a), "r"(b) : "memory");
}
__device__ __forceinline__ uint32_t bf16x2_of(float hi, float lo) {  // upper16=bf16(hi), lower16=bf16(lo)
    uint32_t r; asm("cvt.rn.bf16x2.f32 %0, %1, %2;" : "=r"(r) : "f"(hi), "f"(lo)); return r;
}
__device__ __forceinline__ uint32_t sw128(uint32_t off) { return off ^ ((off >> 3) & 0x70); }

__device__ __forceinline__ void ldsm4(uint32_t addr, uint32_t& r0, uint32_t& r1, uint32_t& r2, uint32_t& r3) {
    asm volatile("ldmatrix.sync.aligned.m8n8.x4.shared.b16 {%0,%1,%2,%3}, [%4];"
                 : "=r"(r0), "=r"(r1), "=r"(r2), "=r"(r3) : "r"(addr));
}
__device__ __forceinline__ void ldsm2(uint32_t addr, uint32_t& r0, uint32_t& r1) {
    asm volatile("ldmatrix.sync.aligned.m8n8.x2.shared.b16 {%0,%1}, [%2];"
                 : "=r"(r0), "=r"(r1) : "r"(addr));
}
__device__ __forceinline__ void mma16816(float* d, uint32_t a0, uint32_t a1, uint32_t a2, uint32_t a3,
                                         uint32_t b0, uint32_t b1) {
    asm volatile("mma.sync.aligned.m16n8k16.row.col.f32.bf16.bf16.f32 "
                 "{%0,%1,%2,%3}, {%4,%5,%6,%7}, {%8,%9}, {%0,%1,%2,%3};"
                 : "+f"(d[0]), "+f"(d[1]), "+f"(d[2]), "+f"(d[3])
                 : "r"(a0), "r"(a1), "r"(a2), "r"(a3), "r"(b0), "r"(b1));
}

// ---------------- kernel 1: NCHW -> NHWC ----------------
__global__ void __launch_bounds__(256) k_transpose(const float* __restrict__ x) {
    __shared__ float sh[64][33];
    int blk = blockIdx.x;
    int b   = blk >> 9;
    int hw0 = (blk & 511) << 5;
    int t = threadIdx.x;
#pragma unroll
    for (int i = 0; i < 8; i++) {
        int e = t + i * 256;
        int c = e >> 5, wp = e & 31;
        sh[c][wp] = x[((size_t)(b * 64 + c) << 14) + hw0 + wp];
    }
    __syncthreads();
#pragma unroll
    for (int i = 0; i < 8; i++) {
        int e = t + i * 256;
        int wp = e >> 6, c = e & 63;
        g_xt[(((size_t)b << 14) + hw0 + wp) * 64 + c] = sh[c][wp];
    }
}

// ---------------- kernel 2: pack w_conv into bf16 hi/lo swizzled tiles ----------------
// per tap: B[o][c] tile (64 rows x 128B, SW128-swizzled). hi at +0, lo at +8192.
__global__ void k_wpack(const float* __restrict__ w_conv) {
    int t = blockIdx.x * 256 + threadIdx.x;
    if (t >= 9 * 4096) return;
    int tap = t >> 12;
    int r   = t & 4095;
    int o = r >> 6, c = r & 63;
    float w = w_conv[o * 576 + c * 9 + tap];
    __nv_bfloat16 hb = __float2bfloat16(w);
    float hf = __bfloat162float(hb);
    __nv_bfloat16 lb = __float2bfloat16(w - hf);
    uint32_t swo = sw128(o * 128 + c * 2);
    char* base = (char*)g_wqs + tap * 16384;
    *(__nv_bfloat16*)(base + swo)        = hb;
    *(__nv_bfloat16*)(base + 8192 + swo) = lb;
}

// ---------------- kernel 3: offset+mask conv (smem-staged NHWC) + corner precompute ----------------
// CTA = 128 threads = one image row (h). 4 channel-chunks of 16.
// xs: 3 rows x 128 w x 16 c (stride 20 floats). shW: [(kk*16+cc)*28 + ch].
#define XS_STRIDE 20
#define CONV_XS_FLOATS (3 * 128 * XS_STRIDE)
#define CONV_W_FLOATS  (9 * 16 * 28)
__global__ void __launch_bounds__(128) k_conv(const float* __restrict__ w_off,
                                              const float* __restrict__ w_msk) {
    extern __shared__ float cs[];
    float* xs  = cs;                    // CONV_XS_FLOATS
    float* shW = cs + CONV_XS_FLOATS;   // CONV_W_FLOATS

    int t = threadIdx.x;
    int h = blockIdx.x & 127;
    int b = blockIdx.x >> 7;
    int w = t;
    const float* xb = g_xt + ((size_t)b << 20);   // NHWC base

    unsigned long long acc[14];
#pragma unroll
    for (int i = 0; i < 14; i++) acc[i] = 0ull;

#pragma unroll 1
    for (int jc = 0; jc < 4; jc++) {
        int c0 = jc << 4;
        __syncthreads();   // previous chunk compute done
        // load weights chunk: 27 ch x 16 cc x 9 kk
        for (int i = t; i < 27 * 16 * 9; i += 128) {
            int ch = i / 144;
            int rem = i - ch * 144;
            int cc = rem / 9, kk = rem - cc * 9;
            float v = (ch < 18) ? w_off[ch * 576 + (c0 + cc) * 9 + kk]
                                : w_msk[(ch - 18) * 576 + (c0 + cc) * 9 + kk];
            shW[(kk * 16 + cc) * 28 + ch] = v;
        }
        for (int i = t; i < 9 * 16; i += 128) shW[i * 28 + 27] = 0.f;
        // load x rows h-1..h+1, 16 channels
#pragma unroll
        for (int i = 0; i < 12; i++) {
            int idx = i * 128 + t;            // over 1536 float4
            int r   = idx >> 9;               // 0..2
            int rem = idx & 511;
            int ww  = rem >> 2, c4 = rem & 3;
            int gh  = h - 1 + r;
            float4 v = make_float4(0.f, 0.f, 0.f, 0.f);
            if ((unsigned)gh < 128u)
                v = *(const float4*)(xb + ((size_t)(gh * 128 + ww) << 6) + c0 + c4 * 4);
            *(float4*)(xs + (r * 128 + ww) * XS_STRIDE + c4 * 4) = v;
        }
        __syncthreads();
        // compute
#pragma unroll 1
        for (int kk = 0; kk < 9; kk++) {
            int dy = kk / 3 - 1, dx = kk % 3 - 1;
            int wc = w + dx;
            if ((unsigned)wc >= 128u) continue;
            const float* xr = xs + ((1 + dy) * 128 + wc) * XS_STRIDE;
            const float* wbase = shW + kk * 16 * 28;
#pragma unroll
            for (int c4 = 0; c4 < 4; c4++) {
                float4 xv = *(const float4*)(xr + c4 * 4);
                float xe[4] = {xv.x, xv.y, xv.z, xv.w};
#pragma unroll
                for (int e = 0; e < 4; e++) {
                    unsigned long long vd = pack2(xe[e], xe[e]);
                    const ulonglong2* wr = (const ulonglong2*)(wbase + (c4 * 4 + e) * 28);
#pragma unroll
                    for (int q = 0; q < 7; q++) {
                        ulonglong2 wp = wr[q];
                        ffma2(acc[2 * q],     vd, wp.x);
                        ffma2(acc[2 * q + 1], vd, wp.y);
                    }
                }
            }
        }
    }

    float rr[28];
#pragma unroll
    for (int q = 0; q < 14; q++) {
        float2 e = unpack2(acc[q]); rr[2 * q] = e.x; rr[2 * q + 1] = e.y;
    }

    int p = b * 16384 + h * 128 + w;
#pragma unroll
    for (int k = 0; k < 9; k++) {
        float oy = rr[2 * k], ox = rr[2 * k + 1];
        float m  = 1.f / (1.f + __expf(-rr[18 + k]));
        float py = (float)(h + k / 3 - 1) + oy;
        float px = (float)(w + k % 3 - 1) + ox;
        float y0f = floorf(py), x0f = floorf(px);
        float wy1 = py - y0f, wy0 = 1.f - wy1;
        float wx1 = px - x0f, wx0 = 1.f - wx1;
        int y0 = (int)y0f, x0i = (int)x0f;
        int y1 = y0 + 1, x1i = x0i + 1;
        bool vy0 = (unsigned)y0  < 128u, vy1 = (unsigned)y1  < 128u;
        bool vx0 = (unsigned)x0i < 128u, vx1 = (unsigned)x1i < 128u;
        int cy0 = min(max(y0, 0), 127), cy1 = min(max(y1, 0), 127);
        int cx0 = min(max(x0i, 0), 127), cx1 = min(max(x1i, 0), 127);
        int4 ci; float4 cw;
        ci.x = cy0 * 128 + cx0; cw.x = (vy0 && vx0) ? m * wy0 * wx0 : 0.f;
        ci.y = cy0 * 128 + cx1; cw.y = (vy0 && vx1) ? m * wy0 * wx1 : 0.f;
        ci.z = cy1 * 128 + cx0; cw.z = (vy1 && vx0) ? m * wy1 * wx0 : 0.f;
        ci.w = cy1 * 128 + cx1; cw.w = (vy1 && vx1) ? m * wy1 * wx1 : 0.f;
        g_ci[(size_t)p * 9 + k] = ci;
        g_cw[(size_t)p * 9 + k] = cw;
    }
}

// ---------------- kernel 4: deformable gather + mma.sync contraction ----------------
// CTA = 128 px, 256 threads (8 warps). Warp w owns px rows [w*16, w*16+16), all 64 o.
// Per tap: gather A[128x64] bf16 hi/lo (SW128 smem), copy B tile, 96 mma/warp (3-pass).
#define A_HI 0
#define A_LO 16384
#define B_HI 32768
#define B_LO 40960
#define DSMEM_TOTAL 49152
__global__ void __launch_bounds__(256) k_deform(float* __restrict__ out) {
    extern __shared__ __align__(1024) char smem[];
    uint32_t sb = smem_u32(smem);

    int t = threadIdx.x, warp = t >> 5, lane = t & 31;
    int P0 = blockIdx.x << 7;
    int b = P0 >> 14, hwbase = P0 & 16383;
    const float* xb = g_xt + ((size_t)b << 20);

    float d[8][4];
#pragma unroll
    for (int nb = 0; nb < 8; nb++)
#pragma unroll
        for (int i = 0; i < 4; i++) d[nb][i] = 0.f;

    // ldmatrix lane-address components
    int a_row = warp * 16 + (lane & 7) + ((lane >> 3) & 1) * 8;
    int a_kx  = ((lane >> 4) & 1) * 16;
    int b_row = lane & 7;
    int b_kx  = ((lane >> 3) & 1) * 16;

#pragma unroll 1
    for (int tap = 0; tap < 9; tap++) {
        __syncthreads();   // previous tap's mma done reading smem
        // copy per-tap weight tile (16KB: hi at B_HI, lo at B_HI+8192)
        {
            const uint4* src = (const uint4*)g_wqs + tap * 1024;
            uint4* dst = (uint4*)(smem + B_HI);
#pragma unroll
            for (int i = 0; i < 4; i++) dst[t + i * 256] = src[t + i * 256];
        }
        // gather A tile: 128 px x 64 c -> bf16 hi/lo
#pragma unroll 2
        for (int it = 0; it < 8; it++) {
            int i = (it << 8) + t;
            int px = i >> 4;
            int cg = i & 15;
            size_t didx = (size_t)(P0 + px) * 9 + tap;
            int4   ci = g_ci[didx];
            float4 cw = g_cw[didx];
            float4 v0 = *((const float4*)(xb + ((size_t)ci.x << 6)) + cg);
            float4 v1 = *((const float4*)(xb + ((size_t)ci.y << 6)) + cg);
            float4 v2 = *((const float4*)(xb + ((size_t)ci.z << 6)) + cg);
            float4 v3 = *((const float4*)(xb + ((size_t)ci.w << 6)) + cg);
            float r0 = cw.x * v0.x + cw.y * v1.x + cw.z * v2.x + cw.w * v3.x;
            float r1 = cw.x * v0.y + cw.y * v1.y + cw.z * v2.y + cw.w * v3.y;
            float r2 = cw.x * v0.z + cw.y * v1.z + cw.z * v2.z + cw.w * v3.z;
            float r3 = cw.x * v0.w + cw.y * v1.w + cw.z * v2.w + cw.w * v3.w;
            uint32_t h01 = bf16x2_of(r1, r0);
            uint32_t h23 = bf16x2_of(r3, r2);
            float hi0 = __uint_as_float(h01 << 16);
            float hi1 = __uint_as_float(h01 & 0xFFFF0000u);
            float hi2 = __uint_as_float(h23 << 16);
            float hi3 = __uint_as_float(h23 & 0xFFFF0000u);
            uint32_t l01 = bf16x2_of(r1 - hi1, r0 - hi0);
            uint32_t l23 = bf16x2_of(r3 - hi3, r2 - hi2);
            uint32_t swo = sw128((uint32_t)(px * 128 + cg * 8));
            sts64(sb + A_HI + swo, h01, h23);
            sts64(sb + A_LO + swo, l01, l23);
        }
        __syncthreads();
        // mma: D[16x64] += A[16x64] * B^T, 3-pass hi/lo
#pragma unroll
        for (int kb = 0; kb < 4; kb++) {
            uint32_t aoff = sw128((uint32_t)(a_row * 128 + kb * 32 + a_kx));
            uint32_t ah0, ah1, ah2, ah3, al0, al1, al2, al3;
            ldsm4(sb + A_HI + aoff, ah0, ah1, ah2, ah3);
            ldsm4(sb + A_LO + aoff, al0, al1, al2, al3);
#pragma unroll
            for (int nb = 0; nb < 8; nb++) {
                uint32_t boff = sw128((uint32_t)((nb * 8 + b_row) * 128 + kb * 32 + b_kx));
                uint32_t bh0, bh1, bl0, bl1;
                ldsm2(sb + B_HI + boff, bh0, bh1);
                ldsm2(sb + B_LO + boff, bl0, bl1);
                mma16816(d[nb], ah0, ah1, ah2, ah3, bh0, bh1);
                mma16816(d[nb], ah0, ah1, ah2, ah3, bl0, bl1);
                mma16816(d[nb], al0, al1, al2, al3, bh0, bh1);
            }
        }
    }

    // epilogue: D frag -> out (NCHW). lane: rows r0=warp*16+(lane>>2), r1=r0+8; cols o0=nb*8+(lane&3)*2.
    size_t bo = (size_t)b << 20;
    int r0 = hwbase + warp * 16 + (lane >> 2);
    int r1 = r0 + 8;
#pragma unroll
    for (int nb = 0; nb < 8; nb++) {
        int o0 = nb * 8 + (lane & 3) * 2;
        out[bo + (size_t)o0 * 16384 + r0]       = d[nb][0];
        out[bo + (size_t)(o0 + 1) * 16384 + r0] = d[nb][1];
        out[bo + (size_t)o0 * 16384 + r1]       = d[nb][2];
        out[bo + (size_t)(o0 + 1) * 16384 + r1] = d[nb][3];
    }
}

// ---------------- launch ----------------
extern "C" void kernel_launch(void* const* d_in, const int* in_sizes, int n_in,
                              void* d_out, int out_size) {
    (void)in_sizes; (void)n_in; (void)out_size;
    const float* x      = (const float*)d_in[0];
    const float* w_conv = (const float*)d_in[1];
    const float* w_off  = (const float*)d_in[2];
    const float* w_msk  = (const float*)d_in[3];
    float* out = (float*)d_out;

    const int convSmem = (CONV_XS_FLOATS + CONV_W_FLOATS) * 4;   // 46848 B
    cudaFuncSetAttribute(k_conv,   cudaFuncAttributeMaxDynamicSharedMemorySize, convSmem);
    cudaFuncSetAttribute(k_deform, cudaFuncAttributeMaxDynamicSharedMemorySize, DSMEM_TOTAL);

    k_transpose<<<4096, 256>>>(x);
    k_wpack<<<(9 * 4096 + 255) / 256, 256>>>(w_conv);
    k_conv<<<1024, 128, convSmem>>>(w_off, w_msk);
    k_deform<<<1024, 256, DSMEM_TOTAL>>>(out);
}

// round 6
// speedup vs baseline: 2.1074x; 1.2960x over previous
#include <cuda_runtime.h>
#include <cuda_bf16.h>
#include <cstdint>

#define HWsz 16384
#define NPIX (8 * HWsz)   // 131072 pixels

// -------- scratch --------
__device__ float    g_xt[(size_t)NPIX * 64];                    // NHWC x
__device__ __align__(16) uint32_t g_wqs[9 * 4096];              // deform W: per tap 16KB (hi 8KB + lo 8KB), 64x64 bf16 SW128
__device__ __align__(16) uint32_t g_wom[9 * 2048];              // conv W: per tap 8KB (hi 4KB + lo 4KB), 32x64 bf16 SW128
__device__ int4     g_ci[(size_t)NPIX * 9];                     // bilinear corner indices
__device__ float4   g_cw[(size_t)NPIX * 9];                     // corner weights (mask folded)

// -------- helpers --------
__device__ __forceinline__ uint32_t smem_u32(const void* p) {
    return (uint32_t)__cvta_generic_to_shared(p);
}
__device__ __forceinline__ void sts64(uint32_t addr, uint32_t a, uint32_t b) {
    asm volatile("st.shared.v2.b32 [%0], {%1, %2};" :: "r"(addr), "r"(a), "r"(b) : "memory");
}
__device__ __forceinline__ uint32_t bf16x2_of(float hi, float lo) {  // upper16=bf16(hi), lower16=bf16(lo)
    uint32_t r; asm("cvt.rn.bf16x2.f32 %0, %1, %2;" : "=r"(r) : "f"(hi), "f"(lo)); return r;
}
__device__ __forceinline__ uint32_t sw128(uint32_t off) { return off ^ ((off >> 3) & 0x70); }

__device__ __forceinline__ void ldsm4(uint32_t addr, uint32_t& r0, uint32_t& r1, uint32_t& r2, uint32_t& r3) {
    asm volatile("ldmatrix.sync.aligned.m8n8.x4.shared.b16 {%0,%1,%2,%3}, [%4];"
                 : "=r"(r0), "=r"(r1), "=r"(r2), "=r"(r3) : "r"(addr));
}
__device__ __forceinline__ void ldsm2(uint32_t addr, uint32_t& r0, uint32_t& r1) {
    asm volatile("ldmatrix.sync.aligned.m8n8.x2.shared.b16 {%0,%1}, [%2];"
                 : "=r"(r0), "=r"(r1) : "r"(addr));
}
__device__ __forceinline__ void mma16816(float* d, uint32_t a0, uint32_t a1, uint32_t a2, uint32_t a3,
                                         uint32_t b0, uint32_t b1) {
    asm volatile("mma.sync.aligned.m16n8k16.row.col.f32.bf16.bf16.f32 "
                 "{%0,%1,%2,%3}, {%4,%5,%6,%7}, {%8,%9}, {%0,%1,%2,%3};"
                 : "+f"(d[0]), "+f"(d[1]), "+f"(d[2]), "+f"(d[3])
                 : "r"(a0), "r"(a1), "r"(a2), "r"(a3), "r"(b0), "r"(b1));
}
// split float into bf16 hi/lo packed pairs
__device__ __forceinline__ void hilo_pack(float r0, float r1, uint32_t& h, uint32_t& l) {
    h = bf16x2_of(r1, r0);
    float hi0 = __uint_as_float(h << 16);
    float hi1 = __uint_as_float(h & 0xFFFF0000u);
    l = bf16x2_of(r1 - hi1, r0 - hi0);
}

// ---------------- kernel 1: NCHW -> NHWC ----------------
__global__ void __launch_bounds__(256) k_transpose(const float* __restrict__ x) {
    __shared__ float sh[64][33];
    int blk = blockIdx.x;
    int b   = blk >> 9;
    int hw0 = (blk & 511) << 5;
    int t = threadIdx.x;
#pragma unroll
    for (int i = 0; i < 8; i++) {
        int e = t + i * 256;
        int c = e >> 5, wp = e & 31;
        sh[c][wp] = x[((size_t)(b * 64 + c) << 14) + hw0 + wp];
    }
    __syncthreads();
#pragma unroll
    for (int i = 0; i < 8; i++) {
        int e = t + i * 256;
        int wp = e >> 6, c = e & 63;
        g_xt[(((size_t)b << 14) + hw0 + wp) * 64 + c] = sh[c][wp];
    }
}

// ---------------- kernel 2a: pack w_conv (deform B tiles, 64x64) ----------------
__global__ void k_wpack(const float* __restrict__ w_conv) {
    int t = blockIdx.x * 256 + threadIdx.x;
    if (t >= 9 * 4096) return;
    int tap = t >> 12;
    int r   = t & 4095;
    int o = r >> 6, c = r & 63;
    float w = w_conv[o * 576 + c * 9 + tap];
    __nv_bfloat16 hb = __float2bfloat16(w);
    __nv_bfloat16 lb = __float2bfloat16(w - __bfloat162float(hb));
    uint32_t swo = sw128(o * 128 + c * 2);
    char* base = (char*)g_wqs + tap * 16384;
    *(__nv_bfloat16*)(base + swo)        = hb;
    *(__nv_bfloat16*)(base + 8192 + swo) = lb;
}

// ---------------- kernel 2b: pack w_offset/w_mask (conv B tiles, 32x64; rows 27..31 zero) ----------------
__global__ void k_wpack2(const float* __restrict__ w_off, const float* __restrict__ w_msk) {
    int t = blockIdx.x * 256 + threadIdx.x;
    if (t >= 9 * 2048) return;
    int tap = t >> 11;
    int r   = t & 2047;
    int o = r >> 6, c = r & 63;
    float w = 0.f;
    if (o < 18)      w = w_off[o * 576 + c * 9 + tap];
    else if (o < 27) w = w_msk[(o - 18) * 576 + c * 9 + tap];
    __nv_bfloat16 hb = __float2bfloat16(w);
    __nv_bfloat16 lb = __float2bfloat16(w - __bfloat162float(hb));
    uint32_t swo = sw128(o * 128 + c * 2);
    char* base = (char*)g_wom + tap * 8192;
    *(__nv_bfloat16*)(base + swo)        = hb;
    *(__nv_bfloat16*)(base + 4096 + swo) = lb;
}

// ---------------- kernel 3: offset+mask conv via MMA + corner precompute ----------------
// CTA = one image row (128 px), 256 threads, 8 warps. Double-buffered taps.
// A buf: 32KB (hi 16KB + lo 16KB); B buf: 8KB (hi 4KB + lo 4KB).
#define C_A(s) ((s) * 32768)
#define C_B(s) (65536 + (s) * 8192)
#define CONV_SMEM 81920
__global__ void __launch_bounds__(256) k_conv() {
    extern __shared__ __align__(1024) char smem[];
    uint32_t sb = smem_u32(smem);

    int t = threadIdx.x, warp = t >> 5, lane = t & 31;
    int h = blockIdx.x & 127;
    int b = blockIdx.x >> 7;
    const float* xb = g_xt + ((size_t)b << 20);

    float d[4][4];
#pragma unroll
    for (int nb = 0; nb < 4; nb++)
#pragma unroll
        for (int i = 0; i < 4; i++) d[nb][i] = 0.f;

    int a_row = warp * 16 + (lane & 7) + ((lane >> 3) & 1) * 8;
    int a_kx  = ((lane >> 4) & 1) * 16;
    int b_row = lane & 7;
    int b_kx  = ((lane >> 3) & 1) * 16;

    // ---- gather lambda (direct NHWC reads, zero-pad at borders) ----
    auto gatherA = [&](int tap, uint32_t dA) {
        int dy = tap / 3 - 1, dx = tap % 3 - 1;
        int hh = h + dy;
        bool okh = (unsigned)hh < 128u;
#pragma unroll 2
        for (int it = 0; it < 8; it++) {
            int i = (it << 8) + t;
            int px = i >> 4, cg = i & 15;
            int wp = px + dx;
            float4 v = make_float4(0.f, 0.f, 0.f, 0.f);
            if (okh && (unsigned)wp < 128u)
                v = *(const float4*)(xb + ((size_t)(hh * 128 + wp) << 6) + cg * 4);
            uint32_t h01, l01, h23, l23;
            hilo_pack(v.x, v.y, h01, l01);
            hilo_pack(v.z, v.w, h23, l23);
            uint32_t swo = sw128((uint32_t)(px * 128 + cg * 8));
            sts64(dA + swo, h01, h23);
            sts64(dA + 16384 + swo, l01, l23);
        }
    };
    auto copyB = [&](int tap, int s) {
        const uint4* src = (const uint4*)g_wom + tap * 512;
        uint4* dst = (uint4*)(smem + C_B(s));
#pragma unroll
        for (int i = 0; i < 2; i++) dst[t + i * 256] = src[t + i * 256];
    };

    copyB(0, 0);
    gatherA(0, sb + C_A(0));
    __syncthreads();

#pragma unroll 1
    for (int tap = 0; tap < 9; tap++) {
        int s = tap & 1;
        uint32_t aB = sb + C_A(s), bB = sb + C_B(s);
#pragma unroll
        for (int kb = 0; kb < 4; kb++) {
            uint32_t aoff = sw128((uint32_t)(a_row * 128 + kb * 32 + a_kx));
            uint32_t ah0, ah1, ah2, ah3, al0, al1, al2, al3;
            ldsm4(aB + aoff, ah0, ah1, ah2, ah3);
            ldsm4(aB + 16384 + aoff, al0, al1, al2, al3);
#pragma unroll
            for (int nb = 0; nb < 4; nb++) {
                uint32_t boff = sw128((uint32_t)((nb * 8 + b_row) * 128 + kb * 32 + b_kx));
                uint32_t bh0, bh1, bl0, bl1;
                ldsm2(bB + boff, bh0, bh1);
                ldsm2(bB + 4096 + boff, bl0, bl1);
                mma16816(d[nb], ah0, ah1, ah2, ah3, bh0, bh1);
                mma16816(d[nb], ah0, ah1, ah2, ah3, bl0, bl1);
                mma16816(d[nb], al0, al1, al2, al3, bh0, bh1);
            }
        }
        if (tap < 8) {
            copyB(tap + 1, s ^ 1);
            gatherA(tap + 1, sb + C_A(s ^ 1));
        }
        __syncthreads();
    }

    // transpose D through smem (reuse buf A0): sD[px][33]
    float* sD = (float*)smem;
    {
        int r0 = warp * 16 + (lane >> 2);
        int r1 = r0 + 8;
#pragma unroll
        for (int nb = 0; nb < 4; nb++) {
            int o0 = nb * 8 + (lane & 3) * 2;
            sD[r0 * 33 + o0]     = d[nb][0];
            sD[r0 * 33 + o0 + 1] = d[nb][1];
            sD[r1 * 33 + o0]     = d[nb][2];
            sD[r1 * 33 + o0 + 1] = d[nb][3];
        }
    }
    __syncthreads();

    if (t < 128) {
        int w = t;
        const float* rr = sD + t * 33;
        int p = b * 16384 + h * 128 + w;
#pragma unroll
        for (int k = 0; k < 9; k++) {
            float oy = rr[2 * k], ox = rr[2 * k + 1];
            float m  = 1.f / (1.f + __expf(-rr[18 + k]));
            float py = (float)(h + k / 3 - 1) + oy;
            float px = (float)(w + k % 3 - 1) + ox;
            float y0f = floorf(py), x0f = floorf(px);
            float wy1 = py - y0f, wy0 = 1.f - wy1;
            float wx1 = px - x0f, wx0 = 1.f - wx1;
            int y0 = (int)y0f, x0i = (int)x0f;
            int y1 = y0 + 1, x1i = x0i + 1;
            bool vy0 = (unsigned)y0  < 128u, vy1 = (unsigned)y1  < 128u;
            bool vx0 = (unsigned)x0i < 128u, vx1 = (unsigned)x1i < 128u;
            int cy0 = min(max(y0, 0), 127), cy1 = min(max(y1, 0), 127);
            int cx0 = min(max(x0i, 0), 127), cx1 = min(max(x1i, 0), 127);
            int4 ci; float4 cw;
            ci.x = cy0 * 128 + cx0; cw.x = (vy0 && vx0) ? m * wy0 * wx0 : 0.f;
            ci.y = cy0 * 128 + cx1; cw.y = (vy0 && vx1) ? m * wy0 * wx1 : 0.f;
            ci.z = cy1 * 128 + cx0; cw.z = (vy1 && vx0) ? m * wy1 * wx0 : 0.f;
            ci.w = cy1 * 128 + cx1; cw.w = (vy1 && vx1) ? m * wy1 * wx1 : 0.f;
            g_ci[(size_t)p * 9 + k] = ci;
            g_cw[(size_t)p * 9 + k] = cw;
        }
    }
}

// ---------------- kernel 4: deformable gather + mma.sync, double-buffered ----------------
// A buf: 32KB (hi 16KB + lo 16KB) x2; B buf: 16KB (hi 8KB + lo 8KB) x2 = 96KB.
#define D_A(s) ((s) * 32768)
#define D_B(s) (65536 + (s) * 16384)
#define DEF_SMEM 98304
__global__ void __launch_bounds__(256) k_deform(float* __restrict__ out) {
    extern __shared__ __align__(1024) char smem[];
    uint32_t sb = smem_u32(smem);

    int t = threadIdx.x, warp = t >> 5, lane = t & 31;
    int P0 = blockIdx.x << 7;
    int b = P0 >> 14, hwbase = P0 & 16383;
    const float* xb = g_xt + ((size_t)b << 20);

    float d[8][4];
#pragma unroll
    for (int nb = 0; nb < 8; nb++)
#pragma unroll
        for (int i = 0; i < 4; i++) d[nb][i] = 0.f;

    int a_row = warp * 16 + (lane & 7) + ((lane >> 3) & 1) * 8;
    int a_kx  = ((lane >> 4) & 1) * 16;
    int b_row = lane & 7;
    int b_kx  = ((lane >> 3) & 1) * 16;

    auto gatherA = [&](int tap, uint32_t dA) {
#pragma unroll 2
        for (int it = 0; it < 8; it++) {
            int i = (it << 8) + t;
            int px = i >> 4, cg = i & 15;
            size_t didx = (size_t)(P0 + px) * 9 + tap;
            int4   ci = g_ci[didx];
            float4 cw = g_cw[didx];
            float4 v0 = *((const float4*)(xb + ((size_t)ci.x << 6)) + cg);
            float4 v1 = *((const float4*)(xb + ((size_t)ci.y << 6)) + cg);
            float4 v2 = *((const float4*)(xb + ((size_t)ci.z << 6)) + cg);
            float4 v3 = *((const float4*)(xb + ((size_t)ci.w << 6)) + cg);
            float r0 = cw.x * v0.x + cw.y * v1.x + cw.z * v2.x + cw.w * v3.x;
            float r1 = cw.x * v0.y + cw.y * v1.y + cw.z * v2.y + cw.w * v3.y;
            float r2 = cw.x * v0.z + cw.y * v1.z + cw.z * v2.z + cw.w * v3.z;
            float r3 = cw.x * v0.w + cw.y * v1.w + cw.z * v2.w + cw.w * v3.w;
            uint32_t h01, l01, h23, l23;
            hilo_pack(r0, r1, h01, l01);
            hilo_pack(r2, r3, h23, l23);
            uint32_t swo = sw128((uint32_t)(px * 128 + cg * 8));
            sts64(dA + swo, h01, h23);
            sts64(dA + 16384 + swo, l01, l23);
        }
    };
    auto copyB = [&](int tap, int s) {
        const uint4* src = (const uint4*)g_wqs + tap * 1024;
        uint4* dst = (uint4*)(smem + D_B(s));
#pragma unroll
        for (int i = 0; i < 4; i++) dst[t + i * 256] = src[t + i * 256];
    };

    copyB(0, 0);
    gatherA(0, sb + D_A(0));
    __syncthreads();

#pragma unroll 1
    for (int tap = 0; tap < 9; tap++) {
        int s = tap & 1;
        uint32_t aB = sb + D_A(s), bB = sb + D_B(s);
#pragma unroll
        for (int kb = 0; kb < 4; kb++) {
            uint32_t aoff = sw128((uint32_t)(a_row * 128 + kb * 32 + a_kx));
            uint32_t ah0, ah1, ah2, ah3, al0, al1, al2, al3;
            ldsm4(aB + aoff, ah0, ah1, ah2, ah3);
            ldsm4(aB + 16384 + aoff, al0, al1, al2, al3);
#pragma unroll
            for (int nb = 0; nb < 8; nb++) {
                uint32_t boff = sw128((uint32_t)((nb * 8 + b_row) * 128 + kb * 32 + b_kx));
                uint32_t bh0, bh1, bl0, bl1;
                ldsm2(bB + boff, bh0, bh1);
                ldsm2(bB + 8192 + boff, bl0, bl1);
                mma16816(d[nb], ah0, ah1, ah2, ah3, bh0, bh1);
                mma16816(d[nb], ah0, ah1, ah2, ah3, bl0, bl1);
                mma16816(d[nb], al0, al1, al2, al3, bh0, bh1);
            }
        }
        if (tap < 8) {
            copyB(tap + 1, s ^ 1);
            gatherA(tap + 1, sb + D_A(s ^ 1));
        }
        __syncthreads();
    }

    // epilogue: D frag -> out (NCHW)
    size_t bo = (size_t)b << 20;
    int r0 = hwbase + warp * 16 + (lane >> 2);
    int r1 = r0 + 8;
#pragma unroll
    for (int nb = 0; nb < 8; nb++) {
        int o0 = nb * 8 + (lane & 3) * 2;
        out[bo + (size_t)o0 * 16384 + r0]       = d[nb][0];
        out[bo + (size_t)(o0 + 1) * 16384 + r0] = d[nb][1];
        out[bo + (size_t)o0 * 16384 + r1]       = d[nb][2];
        out[bo + (size_t)(o0 + 1) * 16384 + r1] = d[nb][3];
    }
}

// ---------------- launch ----------------
extern "C" void kernel_launch(void* const* d_in, const int* in_sizes, int n_in,
                              void* d_out, int out_size) {
    (void)in_sizes; (void)n_in; (void)out_size;
    const float* x      = (const float*)d_in[0];
    const float* w_conv = (const float*)d_in[1];
    const float* w_off  = (const float*)d_in[2];
    const float* w_msk  = (const float*)d_in[3];
    float* out = (float*)d_out;

    cudaFuncSetAttribute(k_conv,   cudaFuncAttributeMaxDynamicSharedMemorySize, CONV_SMEM);
    cudaFuncSetAttribute(k_deform, cudaFuncAttributeMaxDynamicSharedMemorySize, DEF_SMEM);

    k_transpose<<<4096, 256>>>(x);
    k_wpack<<<(9 * 4096 + 255) / 256, 256>>>(w_conv);
    k_wpack2<<<(9 * 2048 + 255) / 256, 256>>>(w_off, w_msk);
    k_conv<<<1024, 256, CONV_SMEM>>>();
    k_deform<<<1024, 256, DEF_SMEM>>>(out);
}

// round 7
// speedup vs baseline: 3.0111x; 1.4288x over previous
#include <cuda_runtime.h>
#include <cuda_bf16.h>
#include <cstdint>

#define HWsz 16384
#define NPIX (8 * HWsz)   // 131072 pixels

// -------- scratch --------
__device__ float            g_xt[(size_t)NPIX * 64];    // NHWC x (f32, for deform bilinear blend)
__device__ __nv_bfloat16    g_xh[(size_t)NPIX * 64];    // NHWC x bf16 hi
__device__ __nv_bfloat16    g_xl[(size_t)NPIX * 64];    // NHWC x bf16 lo
__device__ __align__(16) uint32_t g_wqs[9 * 4096];      // deform W: per tap 16KB (hi 8KB + lo 8KB), 64x64 bf16 SW128
__device__ __align__(16) uint32_t g_wom[9 * 2048];      // conv W: per tap 8KB (hi 4KB + lo 4KB), 32x64 bf16 SW128
__device__ int4   g_ci2[(size_t)9 * NPIX];              // corner indices, [tap][pixel]
__device__ float4 g_cw2[(size_t)9 * NPIX];              // corner weights, [tap][pixel]

// -------- helpers --------
__device__ __forceinline__ uint32_t smem_u32(const void* p) {
    return (uint32_t)__cvta_generic_to_shared(p);
}
__device__ __forceinline__ void sts64(uint32_t addr, uint32_t a, uint32_t b) {
    asm volatile("st.shared.v2.b32 [%0], {%1, %2};" :: "r"(addr), "r"(a), "r"(b) : "memory");
}
__device__ __forceinline__ uint32_t bf16x2_of(float hi, float lo) {
    uint32_t r; asm("cvt.rn.bf16x2.f32 %0, %1, %2;" : "=r"(r) : "f"(hi), "f"(lo)); return r;
}
__device__ __forceinline__ uint32_t sw128(uint32_t off) { return off ^ ((off >> 3) & 0x70); }

__device__ __forceinline__ void ldsm4(uint32_t addr, uint32_t& r0, uint32_t& r1, uint32_t& r2, uint32_t& r3) {
    asm volatile("ldmatrix.sync.aligned.m8n8.x4.shared.b16 {%0,%1,%2,%3}, [%4];"
                 : "=r"(r0), "=r"(r1), "=r"(r2), "=r"(r3) : "r"(addr));
}
__device__ __forceinline__ void ldsm2(uint32_t addr, uint32_t& r0, uint32_t& r1) {
    asm volatile("ldmatrix.sync.aligned.m8n8.x2.shared.b16 {%0,%1}, [%2];"
                 : "=r"(r0), "=r"(r1) : "r"(addr));
}
__device__ __forceinline__ void mma16816(float* d, uint32_t a0, uint32_t a1, uint32_t a2, uint32_t a3,
                                         uint32_t b0, uint32_t b1) {
    asm volatile("mma.sync.aligned.m16n8k16.row.col.f32.bf16.bf16.f32 "
                 "{%0,%1,%2,%3}, {%4,%5,%6,%7}, {%8,%9}, {%0,%1,%2,%3};"
                 : "+f"(d[0]), "+f"(d[1]), "+f"(d[2]), "+f"(d[3])
                 : "r"(a0), "r"(a1), "r"(a2), "r"(a3), "r"(b0), "r"(b1));
}
__device__ __forceinline__ void hilo_pack(float r0, float r1, uint32_t& h, uint32_t& l) {
    h = bf16x2_of(r1, r0);
    float hi0 = __uint_as_float(h << 16);
    float hi1 = __uint_as_float(h & 0xFFFF0000u);
    l = bf16x2_of(r1 - hi1, r0 - hi0);
}
__device__ __forceinline__ void cpasync16(uint32_t dst, const void* src, int srcsize) {
    asm volatile("cp.async.ca.shared.global [%0], [%1], 16, %2;"
                 :: "r"(dst), "l"(src), "r"(srcsize) : "memory");
}
__device__ __forceinline__ void cpcommit() { asm volatile("cp.async.commit_group;" ::: "memory"); }
__device__ __forceinline__ void cpwait0()  { asm volatile("cp.async.wait_group 0;" ::: "memory"); }

// ---------------- kernel 1: NCHW -> NHWC (f32 + bf16 hi/lo) ----------------
__global__ void __launch_bounds__(256) k_transpose(const float* __restrict__ x) {
    __shared__ float sh[64][33];
    int blk = blockIdx.x;
    int b   = blk >> 9;
    int hw0 = (blk & 511) << 5;
    int t = threadIdx.x;
#pragma unroll
    for (int i = 0; i < 8; i++) {
        int e = t + i * 256;
        int c = e >> 5, wp = e & 31;
        sh[c][wp] = x[((size_t)(b * 64 + c) << 14) + hw0 + wp];
    }
    __syncthreads();
#pragma unroll
    for (int i = 0; i < 8; i++) {
        int e = t + i * 256;
        int wp = e >> 6, c = e & 63;
        float v = sh[c][wp];
        size_t idx = (((size_t)b << 14) + hw0 + wp) * 64 + c;
        g_xt[idx] = v;
        __nv_bfloat16 hb = __float2bfloat16(v);
        g_xh[idx] = hb;
        g_xl[idx] = __float2bfloat16(v - __bfloat162float(hb));
    }
}

// ---------------- kernel 2a: pack w_conv (deform B tiles, 64x64) ----------------
__global__ void k_wpack(const float* __restrict__ w_conv) {
    int t = blockIdx.x * 256 + threadIdx.x;
    if (t >= 9 * 4096) return;
    int tap = t >> 12;
    int r   = t & 4095;
    int o = r >> 6, c = r & 63;
    float w = w_conv[o * 576 + c * 9 + tap];
    __nv_bfloat16 hb = __float2bfloat16(w);
    __nv_bfloat16 lb = __float2bfloat16(w - __bfloat162float(hb));
    uint32_t swo = sw128(o * 128 + c * 2);
    char* base = (char*)g_wqs + tap * 16384;
    *(__nv_bfloat16*)(base + swo)        = hb;
    *(__nv_bfloat16*)(base + 8192 + swo) = lb;
}

// ---------------- kernel 2b: pack w_offset/w_mask (conv B tiles, 32x64) ----------------
__global__ void k_wpack2(const float* __restrict__ w_off, const float* __restrict__ w_msk) {
    int t = blockIdx.x * 256 + threadIdx.x;
    if (t >= 9 * 2048) return;
    int tap = t >> 11;
    int r   = t & 2047;
    int o = r >> 6, c = r & 63;
    float w = 0.f;
    if (o < 18)      w = w_off[o * 576 + c * 9 + tap];
    else if (o < 27) w = w_msk[(o - 18) * 576 + c * 9 + tap];
    __nv_bfloat16 hb = __float2bfloat16(w);
    __nv_bfloat16 lb = __float2bfloat16(w - __bfloat162float(hb));
    uint32_t swo = sw128(o * 128 + c * 2);
    char* base = (char*)g_wom + tap * 8192;
    *(__nv_bfloat16*)(base + swo)        = hb;
    *(__nv_bfloat16*)(base + 4096 + swo) = lb;
}

// ---------------- kernel 3: offset+mask conv via MMA, cp.async pipelined ----------------
#define C_A(s) ((s) * 32768)
#define C_B(s) (65536 + (s) * 8192)
#define CONV_SMEM 81920
__global__ void __launch_bounds__(256) k_conv() {
    extern __shared__ __align__(1024) char smem[];
    uint32_t sb = smem_u32(smem);

    int t = threadIdx.x, warp = t >> 5, lane = t & 31;
    int h = blockIdx.x & 127;
    int b = blockIdx.x >> 7;
    const __nv_bfloat16* xh = g_xh + ((size_t)b << 20);
    const __nv_bfloat16* xl = g_xl + ((size_t)b << 20);

    float d[4][4];
#pragma unroll
    for (int nb = 0; nb < 4; nb++)
#pragma unroll
        for (int i = 0; i < 4; i++) d[nb][i] = 0.f;

    int a_row = warp * 16 + (lane & 7) + ((lane >> 3) & 1) * 8;
    int a_kx  = ((lane >> 4) & 1) * 16;
    int b_row = lane & 7;
    int b_kx  = ((lane >> 3) & 1) * 16;

    auto copyA = [&](int tap, int s) {
        int dy = tap / 3 - 1, dx = tap % 3 - 1;
        int hh = h + dy;
        bool okh = (unsigned)hh < 128u;
        const __nv_bfloat16* rh = xh + ((size_t)(hh & 127) << 13);  // row base (*128*64)
        const __nv_bfloat16* rl = xl + ((size_t)(hh & 127) << 13);
        uint32_t dA = sb + C_A(s);
#pragma unroll
        for (int i = 0; i < 4; i++) {
            int u = i * 256 + t;            // 16B unit 0..1023
            int px = u >> 3, cg = u & 7;
            int sx = px + dx;
            int sz = (okh && (unsigned)sx < 128u) ? 16 : 0;
            int sxc = min(max(sx, 0), 127);
            uint32_t dsw = sw128((uint32_t)(px * 128 + cg * 16));
            cpasync16(dA + dsw,         (const char*)(rh + sxc * 64) + cg * 16, sz);
            cpasync16(dA + 16384 + dsw, (const char*)(rl + sxc * 64) + cg * 16, sz);
        }
    };
    auto copyB = [&](int tap, int s) {
        const char* src = (const char*)g_wom + tap * 8192;
        uint32_t dB = sb + C_B(s);
#pragma unroll
        for (int i = 0; i < 2; i++) {
            int u = i * 256 + t;
            cpasync16(dB + u * 16, src + u * 16, 16);
        }
    };

    copyA(0, 0); copyB(0, 0); cpcommit(); cpwait0();
    __syncthreads();

#pragma unroll 1
    for (int tap = 0; tap < 9; tap++) {
        int s = tap & 1;
        if (tap < 8) { copyA(tap + 1, s ^ 1); copyB(tap + 1, s ^ 1); cpcommit(); }
        uint32_t aB = sb + C_A(s), bB = sb + C_B(s);
#pragma unroll
        for (int kb = 0; kb < 4; kb++) {
            uint32_t aoff = sw128((uint32_t)(a_row * 128 + kb * 32 + a_kx));
            uint32_t ah0, ah1, ah2, ah3, al0, al1, al2, al3;
            ldsm4(aB + aoff, ah0, ah1, ah2, ah3);
            ldsm4(aB + 16384 + aoff, al0, al1, al2, al3);
#pragma unroll
            for (int nb = 0; nb < 4; nb++) {
                uint32_t boff = sw128((uint32_t)((nb * 8 + b_row) * 128 + kb * 32 + b_kx));
                uint32_t bh0, bh1, bl0, bl1;
                ldsm2(bB + boff, bh0, bh1);
                ldsm2(bB + 4096 + boff, bl0, bl1);
                mma16816(d[nb], ah0, ah1, ah2, ah3, bh0, bh1);
                mma16816(d[nb], ah0, ah1, ah2, ah3, bl0, bl1);
                mma16816(d[nb], al0, al1, al2, al3, bh0, bh1);
            }
        }
        cpwait0();
        __syncthreads();
    }

    // transpose D through smem: sD[px][33]
    float* sD = (float*)smem;
    {
        int r0 = warp * 16 + (lane >> 2);
        int r1 = r0 + 8;
#pragma unroll
        for (int nb = 0; nb < 4; nb++) {
            int o0 = nb * 8 + (lane & 3) * 2;
            sD[r0 * 33 + o0]     = d[nb][0];
            sD[r0 * 33 + o0 + 1] = d[nb][1];
            sD[r1 * 33 + o0]     = d[nb][2];
            sD[r1 * 33 + o0 + 1] = d[nb][3];
        }
    }
    __syncthreads();

    if (t < 128) {
        int w = t;
        const float* rr = sD + t * 33;
        int p = b * 16384 + h * 128 + w;
#pragma unroll
        for (int k = 0; k < 9; k++) {
            float oy = rr[2 * k], ox = rr[2 * k + 1];
            float m  = 1.f / (1.f + __expf(-rr[18 + k]));
            float py = (float)(h + k / 3 - 1) + oy;
            float px = (float)(w + k % 3 - 1) + ox;
            float y0f = floorf(py), x0f = floorf(px);
            float wy1 = py - y0f, wy0 = 1.f - wy1;
            float wx1 = px - x0f, wx0 = 1.f - wx1;
            int y0 = (int)y0f, x0i = (int)x0f;
            int y1 = y0 + 1, x1i = x0i + 1;
            bool vy0 = (unsigned)y0  < 128u, vy1 = (unsigned)y1  < 128u;
            bool vx0 = (unsigned)x0i < 128u, vx1 = (unsigned)x1i < 128u;
            int cy0 = min(max(y0, 0), 127), cy1 = min(max(y1, 0), 127);
            int cx0 = min(max(x0i, 0), 127), cx1 = min(max(x1i, 0), 127);
            int4 ci; float4 cw;
            ci.x = cy0 * 128 + cx0; cw.x = (vy0 && vx0) ? m * wy0 * wx0 : 0.f;
            ci.y = cy0 * 128 + cx1; cw.y = (vy0 && vx1) ? m * wy0 * wx1 : 0.f;
            ci.z = cy1 * 128 + cx0; cw.z = (vy1 && vx0) ? m * wy1 * wx0 : 0.f;
            ci.w = cy1 * 128 + cx1; cw.w = (vy1 && vx1) ? m * wy1 * wx1 : 0.f;
            g_ci2[(size_t)k * NPIX + p] = ci;
            g_cw2[(size_t)k * NPIX + p] = cw;
        }
    }
}

// ---------------- kernel 4: deform gather + mma, register-staged pipeline ----------------
// smem: A x2 (32KB each), B x2 (16KB each), ci/cw slots x2 (4KB each) = 104KB
#define D_A(s)  ((s) * 32768)
#define D_B(s)  (65536 + (s) * 16384)
#define D_CI(s) (98304 + (s) * 4096)
#define DEF_SMEM 106496
__global__ void __launch_bounds__(256, 2) k_deform(float* __restrict__ out) {
    extern __shared__ __align__(1024) char smem[];
    uint32_t sb = smem_u32(smem);

    int t = threadIdx.x, warp = t >> 5, lane = t & 31;
    int P0 = blockIdx.x << 7;
    int b = P0 >> 14, hwbase = P0 & 16383;
    const float* xb = g_xt + ((size_t)b << 20);

    float d[8][4];
#pragma unroll
    for (int nb = 0; nb < 8; nb++)
#pragma unroll
        for (int i = 0; i < 4; i++) d[nb][i] = 0.f;

    int a_row = warp * 16 + (lane & 7) + ((lane >> 3) & 1) * 8;
    int a_kx  = ((lane >> 4) & 1) * 16;
    int b_row = lane & 7;
    int b_kx  = ((lane >> 3) & 1) * 16;

    auto prefetchCI = [&](int tap, int s) {
        uint32_t dst = sb + D_CI(s);
        if (t < 128) cpasync16(dst + t * 16, g_ci2 + (size_t)tap * NPIX + P0 + t, 16);
        else         cpasync16(dst + 2048 + (t - 128) * 16, g_cw2 + (size_t)tap * NPIX + P0 + (t - 128), 16);
    };
    auto copyB = [&](int tap, int s) {
        const char* src = (const char*)g_wqs + tap * 16384;
        uint32_t dB = sb + D_B(s);
#pragma unroll
        for (int i = 0; i < 4; i++) {
            int u = i * 256 + t;
            cpasync16(dB + u * 16, src + u * 16, 16);
        }
    };

    // staged gather state (2 items in flight)
    float4 vv[2][4]; float4 cwq[2]; uint32_t swoq[2];
    auto issue2 = [&](int ciS, int it0) {
        const int4*   sCI = (const int4*)(smem + D_CI(ciS));
        const float4* sCW = (const float4*)(smem + D_CI(ciS) + 2048);
#pragma unroll
        for (int q = 0; q < 2; q++) {
            int i = ((it0 + q) << 8) + t;
            int px = i >> 4, cg = i & 15;
            int4 ci = sCI[px];
            cwq[q]  = sCW[px];
            vv[q][0] = *((const float4*)(xb + ((size_t)ci.x << 6)) + cg);
            vv[q][1] = *((const float4*)(xb + ((size_t)ci.y << 6)) + cg);
            vv[q][2] = *((const float4*)(xb + ((size_t)ci.z << 6)) + cg);
            vv[q][3] = *((const float4*)(xb + ((size_t)ci.w << 6)) + cg);
            swoq[q] = sw128((uint32_t)(px * 128 + cg * 8));
        }
    };
    auto flush2 = [&](uint32_t dA) {
#pragma unroll
        for (int q = 0; q < 2; q++) {
            float4 cw = cwq[q];
            float r0 = cw.x * vv[q][0].x + cw.y * vv[q][1].x + cw.z * vv[q][2].x + cw.w * vv[q][3].x;
            float r1 = cw.x * vv[q][0].y + cw.y * vv[q][1].y + cw.z * vv[q][2].y + cw.w * vv[q][3].y;
            float r2 = cw.x * vv[q][0].z + cw.y * vv[q][1].z + cw.z * vv[q][2].z + cw.w * vv[q][3].z;
            float r3 = cw.x * vv[q][0].w + cw.y * vv[q][1].w + cw.z * vv[q][2].w + cw.w * vv[q][3].w;
            uint32_t h01, l01, h23, l23;
            hilo_pack(r0, r1, h01, l01);
            hilo_pack(r2, r3, h23, l23);
            sts64(dA + swoq[q], h01, h23);
            sts64(dA + 16384 + swoq[q], l01, l23);
        }
    };
    auto do_kb = [&](int kb, uint32_t aB, uint32_t bB) {
        uint32_t aoff = sw128((uint32_t)(a_row * 128 + kb * 32 + a_kx));
        uint32_t ah0, ah1, ah2, ah3, al0, al1, al2, al3;
        ldsm4(aB + aoff, ah0, ah1, ah2, ah3);
        ldsm4(aB + 16384 + aoff, al0, al1, al2, al3);
#pragma unroll
        for (int nb = 0; nb < 8; nb++) {
            uint32_t boff = sw128((uint32_t)((nb * 8 + b_row) * 128 + kb * 32 + b_kx));
            uint32_t bh0, bh1, bl0, bl1;
            ldsm2(bB + boff, bh0, bh1);
            ldsm2(bB + 8192 + boff, bl0, bl1);
            mma16816(d[nb], ah0, ah1, ah2, ah3, bh0, bh1);
            mma16816(d[nb], ah0, ah1, ah2, ah3, bl0, bl1);
            mma16816(d[nb], al0, al1, al2, al3, bh0, bh1);
        }
    };

    // ---- prologue ----
    prefetchCI(0, 0); copyB(0, 0); cpcommit(); cpwait0();
    __syncthreads();
    {   // full gather tap 0 -> A0
        const int4*   sCI = (const int4*)(smem + D_CI(0));
        const float4* sCW = (const float4*)(smem + D_CI(0) + 2048);
        uint32_t dA = sb + D_A(0);
#pragma unroll 2
        for (int it = 0; it < 8; it++) {
            int i = (it << 8) + t;
            int px = i >> 4, cg = i & 15;
            int4 ci = sCI[px];
            float4 cw = sCW[px];
            float4 v0 = *((const float4*)(xb + ((size_t)ci.x << 6)) + cg);
            float4 v1 = *((const float4*)(xb + ((size_t)ci.y << 6)) + cg);
            float4 v2 = *((const float4*)(xb + ((size_t)ci.z << 6)) + cg);
            float4 v3 = *((const float4*)(xb + ((size_t)ci.w << 6)) + cg);
            float r0 = cw.x * v0.x + cw.y * v1.x + cw.z * v2.x + cw.w * v3.x;
            float r1 = cw.x * v0.y + cw.y * v1.y + cw.z * v2.y + cw.w * v3.y;
            float r2 = cw.x * v0.z + cw.y * v1.z + cw.z * v2.z + cw.w * v3.z;
            float r3 = cw.x * v0.w + cw.y * v1.w + cw.z * v2.w + cw.w * v3.w;
            uint32_t h01, l01, h23, l23;
            hilo_pack(r0, r1, h01, l01);
            hilo_pack(r2, r3, h23, l23);
            uint32_t swo = sw128((uint32_t)(px * 128 + cg * 8));
            sts64(dA + swo, h01, h23);
            sts64(dA + 16384 + swo, l01, l23);
        }
    }
    prefetchCI(1, 1); cpcommit(); cpwait0();
    __syncthreads();

    // ---- main loop ----
#pragma unroll 1
    for (int tap = 0; tap < 9; tap++) {
        int s = tap & 1;
        uint32_t aB = sb + D_A(s), bB = sb + D_B(s);
        if (tap < 8) {
            copyB(tap + 1, s ^ 1);               // read next iter from buf s^1
            if (tap + 2 <= 8) prefetchCI(tap + 2, s);  // read next iter's gather
            cpcommit();
        }
        uint32_t dA = sb + D_A(s ^ 1);
        if (tap < 8) issue2(s ^ 1, 0);
        do_kb(0, aB, bB);
        if (tap < 8) { flush2(dA); issue2(s ^ 1, 2); }
        do_kb(1, aB, bB);
        if (tap < 8) { flush2(dA); issue2(s ^ 1, 4); }
        do_kb(2, aB, bB);
        if (tap < 8) { flush2(dA); issue2(s ^ 1, 6); }
        do_kb(3, aB, bB);
        if (tap < 8) flush2(dA);
        cpwait0();
        __syncthreads();
    }

    // epilogue: D frag -> out (NCHW)
    size_t bo = (size_t)b << 20;
    int r0 = hwbase + warp * 16 + (lane >> 2);
    int r1 = r0 + 8;
#pragma unroll
    for (int nb = 0; nb < 8; nb++) {
        int o0 = nb * 8 + (lane & 3) * 2;
        out[bo + (size_t)o0 * 16384 + r0]       = d[nb][0];
        out[bo + (size_t)(o0 + 1) * 16384 + r0] = d[nb][1];
        out[bo + (size_t)o0 * 16384 + r1]       = d[nb][2];
        out[bo + (size_t)(o0 + 1) * 16384 + r1] = d[nb][3];
    }
}

// ---------------- launch ----------------
extern "C" void kernel_launch(void* const* d_in, const int* in_sizes, int n_in,
                              void* d_out, int out_size) {
    (void)in_sizes; (void)n_in; (void)out_size;
    const float* x      = (const float*)d_in[0];
    const float* w_conv = (const float*)d_in[1];
    const float* w_off  = (const float*)d_in[2];
    const float* w_msk  = (const float*)d_in[3];
    float* out = (float*)d_out;

    cudaFuncSetAttribute(k_conv,   cudaFuncAttributeMaxDynamicSharedMemorySize, CONV_SMEM);
    cudaFuncSetAttribute(k_deform, cudaFuncAttributeMaxDynamicSharedMemorySize, DEF_SMEM);

    k_transpose<<<4096, 256>>>(x);
    k_wpack<<<(9 * 4096 + 255) / 256, 256>>>(w_conv);
    k_wpack2<<<(9 * 2048 + 255) / 256, 256>>>(w_off, w_msk);
    k_conv<<<1024, 256, CONV_SMEM>>>();
    k_deform<<<1024, 256, DEF_SMEM>>>(out);
}